// round 9
// baseline (speedup 1.0000x reference)
#include <cuda_runtime.h>
#include <cuda_bf16.h>
#include <cstdint>
#include <math.h>

#define BATCH 4
#define T_SEQ 2048
#define NH 12
#define DMODEL 768
#define DH 64
#define M_ROWS (BATCH * T_SEQ)          // 8192
#define QKV_N (3 * DMODEL)              // 2304
#define GK DMODEL                       // GEMM K = 768

// ------------------------- scratch (static, allocation-free) ---------------
__device__ __nv_bfloat16 g_qkvh[(size_t)M_ROWS * QKV_N];
__device__ __nv_bfloat16 g_qkvl[(size_t)M_ROWS * QKV_N];
__device__ __nv_bfloat16 g_xh[(size_t)M_ROWS * DMODEL];
__device__ __nv_bfloat16 g_xl[(size_t)M_ROWS * DMODEL];
__device__ __nv_bfloat16 g_yh[(size_t)M_ROWS * DMODEL];
__device__ __nv_bfloat16 g_yl[(size_t)M_ROWS * DMODEL];
__device__ __nv_bfloat16 g_wah[(size_t)QKV_N * DMODEL];  // w_attn^T [2304,768]
__device__ __nv_bfloat16 g_wal[(size_t)QKV_N * DMODEL];
__device__ __nv_bfloat16 g_wph[(size_t)DMODEL * DMODEL]; // w_proj^T [768,768]
__device__ __nv_bfloat16 g_wpl[(size_t)DMODEL * DMODEL];

// ------------------------- helpers -----------------------------------------
__device__ __forceinline__ uint32_t smem_u32(const void* p) {
    uint32_t a;
    asm("{ .reg .u64 t; cvta.to.shared.u64 t, %1; cvt.u32.u64 %0, t; }" : "=r"(a) : "l"(p));
    return a;
}
__device__ __forceinline__ void cp16(uint32_t dst, const void* src) {
    asm volatile("cp.async.cg.shared.global [%0], [%1], 16;" :: "r"(dst), "l"(src));
}
#define CP_COMMIT() asm volatile("cp.async.commit_group;" ::: "memory")
#define CP_WAIT0()  asm volatile("cp.async.wait_group 0;" ::: "memory")
#define CP_WAIT1()  asm volatile("cp.async.wait_group 1;" ::: "memory")

__device__ __forceinline__ void ldsm_x4(uint32_t& r0, uint32_t& r1,
                                        uint32_t& r2, uint32_t& r3, uint32_t addr) {
    asm volatile("ldmatrix.sync.aligned.m8n8.x4.shared.b16 {%0,%1,%2,%3}, [%4];"
                 : "=r"(r0), "=r"(r1), "=r"(r2), "=r"(r3) : "r"(addr));
}
__device__ __forceinline__ void ldsm_x4_t(uint32_t& r0, uint32_t& r1,
                                          uint32_t& r2, uint32_t& r3, uint32_t addr) {
    asm volatile("ldmatrix.sync.aligned.m8n8.x4.trans.shared.b16 {%0,%1,%2,%3}, [%4];"
                 : "=r"(r0), "=r"(r1), "=r"(r2), "=r"(r3) : "r"(addr));
}
__device__ __forceinline__ void mma_bf16(float* c, const uint32_t* a,
                                         uint32_t b0, uint32_t b1) {
    asm volatile(
        "mma.sync.aligned.m16n8k16.row.col.f32.bf16.bf16.f32 "
        "{%0,%1,%2,%3}, {%4,%5,%6,%7}, {%8,%9}, {%0,%1,%2,%3};"
        : "+f"(c[0]), "+f"(c[1]), "+f"(c[2]), "+f"(c[3])
        : "r"(a[0]), "r"(a[1]), "r"(a[2]), "r"(a[3]), "r"(b0), "r"(b1));
}
__device__ __forceinline__ void pack_hl(float f0, float f1, uint32_t& h, uint32_t& l) {
    __nv_bfloat16 h0 = __float2bfloat16(f0), h1 = __float2bfloat16(f1);
    __nv_bfloat162 hh; hh.x = h0; hh.y = h1;
    h = *(uint32_t*)&hh;
    __nv_bfloat162 ll;
    ll.x = __float2bfloat16(f0 - __bfloat162float(h0));
    ll.y = __float2bfloat16(f1 - __bfloat162float(h1));
    l = *(uint32_t*)&ll;
}

// ---------------------------------------------------------------------------
// HMMA GEMM, bf16x3, 2-stage cp.async pipeline.
// C = Ah*Bh + Al*Bh + Ah*Bl + bias. K-chunk 32, double-buffered smem.
// 256 threads = 8 warps (4M x 2N), warp tile 32x64. 2 CTAs/SM.
// ---------------------------------------------------------------------------
#define GPAD 40                          // bf16 row stride (80 B), conflict-free
#define GTILE_E (128 * GPAD)             // elements per tile
#define GBUF_E (4 * GTILE_E)             // Ah|Al|Bh|Bl
#define GEMM_SMEM (2 * GBUF_E * 2)       // 81920 bytes

__global__ __launch_bounds__(256, 2) void mma_gemm_kernel(
    const __nv_bfloat16* __restrict__ Ah, const __nv_bfloat16* __restrict__ Al,
    const __nv_bfloat16* __restrict__ Bh, const __nv_bfloat16* __restrict__ Bl,
    const float* __restrict__ bias, float* __restrict__ C,
    __nv_bfloat16* __restrict__ Ch, __nv_bfloat16* __restrict__ Cl, int N)
{
    extern __shared__ __nv_bfloat16 gsm[];
    const int tid  = threadIdx.x;
    const int wid  = tid >> 5;
    const int lane = tid & 31;
    const int m0 = blockIdx.y * 128;
    const int n0 = blockIdx.x * 128;
    const int warp_m = (wid >> 1) * 32;
    const int warp_n = (wid & 1) * 64;
    const uint32_t sbase = smem_u32(gsm);

    const int a_row = (lane & 15);
    const int a_coff = (lane >> 4) * 8;
    const int b_row = (lane & 7) + ((lane >> 3) & 1) * 8;
    const int b_coff = ((lane >> 4) & 1) * 8;

    // per-thread cp.async indices: 2048 ops / 256 thr = 8; idx = tid + it*256
    // tile = idx>>9 (0:Ah 1:Al 2:Bh 3:Bl), row = (idx>>2)&127, g = idx&3
    float acc[2][8][4];
    #pragma unroll
    for (int mi = 0; mi < 2; mi++)
        #pragma unroll
        for (int nj = 0; nj < 8; nj++)
            #pragma unroll
            for (int q = 0; q < 4; q++) acc[mi][nj][q] = 0.0f;

    const int NCHUNK = GK / 32;          // 24

    // ---- preload chunk 0 ----
    #pragma unroll
    for (int it = 0; it < 8; it++) {
        int idx = tid + it * 256;
        int tile = idx >> 9;
        int row = (idx >> 2) & 127;
        int g = idx & 3;
        const __nv_bfloat16* sp =
            (tile == 0) ? Ah : (tile == 1) ? Al : (tile == 2) ? Bh : Bl;
        int rbase = (tile < 2) ? m0 : n0;
        cp16(sbase + (uint32_t)(tile * GTILE_E + row * GPAD + g * 8) * 2,
             sp + (size_t)(rbase + row) * GK + g * 8);
    }
    CP_COMMIT();

    #pragma unroll 1
    for (int ic = 0; ic < NCHUNK; ic++) {
        const uint32_t cbuf = (ic & 1) * GBUF_E;
        if (ic + 1 < NCHUNK) {
            const uint32_t nbuf = ((ic + 1) & 1) * GBUF_E;
            const int kc = (ic + 1) * 32;
            #pragma unroll
            for (int it = 0; it < 8; it++) {
                int idx = tid + it * 256;
                int tile = idx >> 9;
                int row = (idx >> 2) & 127;
                int g = idx & 3;
                const __nv_bfloat16* sp =
                    (tile == 0) ? Ah : (tile == 1) ? Al : (tile == 2) ? Bh : Bl;
                int rbase = (tile < 2) ? m0 : n0;
                cp16(sbase + (uint32_t)(nbuf + tile * GTILE_E + row * GPAD + g * 8) * 2,
                     sp + (size_t)(rbase + row) * GK + kc + g * 8);
            }
            CP_COMMIT();
            CP_WAIT1();
        } else {
            CP_WAIT0();
        }
        __syncthreads();

        #pragma unroll
        for (int ks = 0; ks < 2; ks++) {
            const int k0 = ks * 16;
            uint32_t rah[2][4], ral[2][4];
            #pragma unroll
            for (int mi = 0; mi < 2; mi++) {
                uint32_t ar = cbuf + (warp_m + mi * 16 + a_row) * GPAD + k0 + a_coff;
                ldsm_x4(rah[mi][0], rah[mi][1], rah[mi][2], rah[mi][3],
                        sbase + ar * 2);
                ldsm_x4(ral[mi][0], ral[mi][1], ral[mi][2], ral[mi][3],
                        sbase + (ar + GTILE_E) * 2);
            }
            #pragma unroll
            for (int nb = 0; nb < 4; nb++) {
                uint32_t br = cbuf + 2 * GTILE_E +
                              (warp_n + nb * 16 + b_row) * GPAD + k0 + b_coff;
                uint32_t rb[4];
                ldsm_x4(rb[0], rb[1], rb[2], rb[3], sbase + br * 2);
                #pragma unroll
                for (int mi = 0; mi < 2; mi++)
                    #pragma unroll
                    for (int lo = 0; lo < 2; lo++) {
                        mma_bf16(acc[mi][2 * nb + lo], rah[mi], rb[lo], rb[lo + 2]);
                        mma_bf16(acc[mi][2 * nb + lo], ral[mi], rb[lo], rb[lo + 2]);
                    }
                ldsm_x4(rb[0], rb[1], rb[2], rb[3], sbase + (br + GTILE_E) * 2);
                #pragma unroll
                for (int mi = 0; mi < 2; mi++)
                    #pragma unroll
                    for (int lo = 0; lo < 2; lo++)
                        mma_bf16(acc[mi][2 * nb + lo], rah[mi], rb[lo], rb[lo + 2]);
            }
        }
        __syncthreads();
    }

    const int mrow = m0 + warp_m + (lane >> 2);
    const int ncol = n0 + warp_n + (lane & 3) * 2;
    #pragma unroll
    for (int mi = 0; mi < 2; mi++) {
        #pragma unroll
        for (int nj = 0; nj < 8; nj++) {
            int r = mrow + mi * 16;
            int c = ncol + nj * 8;
            float bv0 = bias[c], bv1 = bias[c + 1];
            float v00 = acc[mi][nj][0] + bv0, v01 = acc[mi][nj][1] + bv1;
            float v10 = acc[mi][nj][2] + bv0, v11 = acc[mi][nj][3] + bv1;
            if (Cl) {
                uint32_t h0, l0, h1, l1;
                pack_hl(v00, v01, h0, l0);
                pack_hl(v10, v11, h1, l1);
                *(uint32_t*)(Ch + (size_t)r * N + c) = h0;
                *(uint32_t*)(Cl + (size_t)r * N + c) = l0;
                *(uint32_t*)(Ch + (size_t)(r + 8) * N + c) = h1;
                *(uint32_t*)(Cl + (size_t)(r + 8) * N + c) = l1;
            } else {
                *(float2*)(C + (size_t)r * N + c) = make_float2(v00, v01);
                *(float2*)(C + (size_t)(r + 8) * N + c) = make_float2(v10, v11);
            }
        }
    }
}

// ---------------------------------------------------------------------------
// HMMA flash attention (causal), bf16x3, double-buffered K/V pipeline.
// Grid (T/128, B*NH), 256 threads = 8 warps x 16 Q-rows. K/V tiles 64 rows.
// ---------------------------------------------------------------------------
#define APAD 72
#define AQH 0
#define AQL (128 * APAD)
#define AKV0 (2 * 128 * APAD)            // start of KV buffer 0
#define AKV_T (64 * APAD)                // one tile (Kh/Kl/Vh/Vl)
#define AKV_B (4 * AKV_T)                // one KV buffer
#define ATTN_SMEM ((AKV0 + 2 * AKV_B) * 2)   // 110592 bytes

__global__ __launch_bounds__(256, 2) void mma_attn_kernel(
    const __nv_bfloat16* __restrict__ qkvh, const __nv_bfloat16* __restrict__ qkvl,
    __nv_bfloat16* __restrict__ yh, __nv_bfloat16* __restrict__ yl)
{
    extern __shared__ __nv_bfloat16 sm[];
    const int tid = threadIdx.x;
    const int wid = tid >> 5;
    const int lane = tid & 31;
    const int qt = gridDim.x - 1 - blockIdx.x;     // heavy tiles first
    const int bh = blockIdx.y;
    const int b = bh / NH;
    const int h = bh % NH;
    const size_t base = (size_t)b * T_SEQ * QKV_N;
    const int qoff = h * DH;
    const int koff = DMODEL + h * DH;
    const int voff = 2 * DMODEL + h * DH;
    const uint32_t sbase = smem_u32(sm);

    const int a_row = (lane & 15);
    const int a_coff = (lane >> 4) * 8;
    const int b_row = (lane & 7) + ((lane >> 3) & 1) * 8;
    const int b_coff = ((lane >> 4) & 1) * 8;
    const int v_krow = ((lane >> 3) & 1) * 8 + (lane & 7);
    const int v_ncol = ((lane >> 4) & 1) * 8;

    // ---- Q tile (hi/lo), its own cp.async group ----
    #pragma unroll
    for (int it = 0; it < 4; it++) {
        int idx = tid + it * 256;        // 0..1023
        int row = idx >> 3, g = idx & 7;
        size_t goff = base + (size_t)(qt * 128 + row) * QKV_N + qoff + g * 8;
        uint32_t so = (uint32_t)(row * APAD + g * 8) * 2;
        cp16(sbase + so, qkvh + goff);
        cp16(sbase + AQL * 2 + so, qkvl + goff);
    }
    CP_COMMIT();

    const int nkt = 2 * qt + 2;

    // ---- preload KV chunk 0 ----
    #pragma unroll
    for (int it = 0; it < 8; it++) {
        int idx = tid + it * 256;
        int tile = idx >> 9;
        int r = (idx >> 3) & 63;
        int g = idx & 7;
        const __nv_bfloat16* src = (tile & 1) ? qkvl : qkvh;
        int off = (tile < 2) ? koff : voff;
        cp16(sbase + (uint32_t)(AKV0 + tile * AKV_T + r * APAD + g * 8) * 2,
             src + base + (size_t)r * QKV_N + off + g * 8);
    }
    CP_COMMIT();

    float oacc[8][4];
    #pragma unroll
    for (int nj = 0; nj < 8; nj++)
        #pragma unroll
        for (int q = 0; q < 4; q++) oacc[nj][q] = 0.0f;
    float m_a = -1e30f, m_b = -1e30f, l_a = 0.0f, l_b = 0.0f;

    const int gr_a = qt * 128 + wid * 16 + (lane >> 2);
    const int gr_b = gr_a + 8;

    #pragma unroll 1
    for (int kt = 0; kt < nkt; kt++) {
        const uint32_t kvb = AKV0 + (kt & 1) * AKV_B;
        if (kt + 1 < nkt) {
            const uint32_t nbuf = AKV0 + ((kt + 1) & 1) * AKV_B;
            #pragma unroll
            for (int it = 0; it < 8; it++) {
                int idx = tid + it * 256;
                int tile = idx >> 9;
                int r = (idx >> 3) & 63;
                int g = idx & 7;
                const __nv_bfloat16* src = (tile & 1) ? qkvl : qkvh;
                int off = (tile < 2) ? koff : voff;
                cp16(sbase + (uint32_t)(nbuf + tile * AKV_T + r * APAD + g * 8) * 2,
                     src + base + (size_t)((kt + 1) * 64 + r) * QKV_N + off + g * 8);
            }
            CP_COMMIT();
            CP_WAIT1();
        } else {
            CP_WAIT0();
        }
        __syncthreads();

        // ---- S = Qh*Kh + Ql*Kh + Qh*Kl ----
        float sacc[8][4];
        #pragma unroll
        for (int nj = 0; nj < 8; nj++)
            #pragma unroll
            for (int q = 0; q < 4; q++) sacc[nj][q] = 0.0f;

        #pragma unroll
        for (int ks = 0; ks < 4; ks++) {
            const int k0 = ks * 16;
            uint32_t qh[4], ql[4];
            uint32_t qr = (wid * 16 + a_row) * APAD + k0 + a_coff;
            ldsm_x4(qh[0], qh[1], qh[2], qh[3], sbase + qr * 2);
            ldsm_x4(ql[0], ql[1], ql[2], ql[3], sbase + (AQL + qr) * 2);
            #pragma unroll
            for (int nb = 0; nb < 4; nb++) {
                uint32_t br = kvb + (nb * 16 + b_row) * APAD + k0 + b_coff;
                uint32_t rb[4];
                ldsm_x4(rb[0], rb[1], rb[2], rb[3], sbase + br * 2);
                #pragma unroll
                for (int lo = 0; lo < 2; lo++) {
                    mma_bf16(sacc[2 * nb + lo], qh, rb[lo], rb[lo + 2]);
                    mma_bf16(sacc[2 * nb + lo], ql, rb[lo], rb[lo + 2]);
                }
                ldsm_x4(rb[0], rb[1], rb[2], rb[3], sbase + (br + AKV_T) * 2);
                #pragma unroll
                for (int lo = 0; lo < 2; lo++)
                    mma_bf16(sacc[2 * nb + lo], qh, rb[lo], rb[lo + 2]);
            }
        }

        // ---- scale + causal mask ----
        const bool diag = (kt >= 2 * qt);
        #pragma unroll
        for (int nj = 0; nj < 8; nj++) {
            #pragma unroll
            for (int q = 0; q < 4; q++) sacc[nj][q] *= 0.125f;
            if (diag) {
                int gc = kt * 64 + nj * 8 + (lane & 3) * 2;
                if (gc > gr_a)     sacc[nj][0] = -1e30f;
                if (gc + 1 > gr_a) sacc[nj][1] = -1e30f;
                if (gc > gr_b)     sacc[nj][2] = -1e30f;
                if (gc + 1 > gr_b) sacc[nj][3] = -1e30f;
            }
        }

        // ---- online softmax ----
        float mx_a = -1e30f, mx_b = -1e30f;
        #pragma unroll
        for (int nj = 0; nj < 8; nj++) {
            mx_a = fmaxf(mx_a, fmaxf(sacc[nj][0], sacc[nj][1]));
            mx_b = fmaxf(mx_b, fmaxf(sacc[nj][2], sacc[nj][3]));
        }
        mx_a = fmaxf(mx_a, __shfl_xor_sync(0xffffffffu, mx_a, 1));
        mx_a = fmaxf(mx_a, __shfl_xor_sync(0xffffffffu, mx_a, 2));
        mx_b = fmaxf(mx_b, __shfl_xor_sync(0xffffffffu, mx_b, 1));
        mx_b = fmaxf(mx_b, __shfl_xor_sync(0xffffffffu, mx_b, 2));
        float mn_a = fmaxf(m_a, mx_a), mn_b = fmaxf(m_b, mx_b);
        float corr_a = __expf(m_a - mn_a), corr_b = __expf(m_b - mn_b);
        float sum_a = 0.0f, sum_b = 0.0f;
        #pragma unroll
        for (int nj = 0; nj < 8; nj++) {
            sacc[nj][0] = __expf(sacc[nj][0] - mn_a);
            sacc[nj][1] = __expf(sacc[nj][1] - mn_a);
            sacc[nj][2] = __expf(sacc[nj][2] - mn_b);
            sacc[nj][3] = __expf(sacc[nj][3] - mn_b);
            sum_a += sacc[nj][0] + sacc[nj][1];
            sum_b += sacc[nj][2] + sacc[nj][3];
        }
        sum_a += __shfl_xor_sync(0xffffffffu, sum_a, 1);
        sum_a += __shfl_xor_sync(0xffffffffu, sum_a, 2);
        sum_b += __shfl_xor_sync(0xffffffffu, sum_b, 1);
        sum_b += __shfl_xor_sync(0xffffffffu, sum_b, 2);
        l_a = l_a * corr_a + sum_a;
        l_b = l_b * corr_b + sum_b;
        m_a = mn_a; m_b = mn_b;
        #pragma unroll
        for (int nj = 0; nj < 8; nj++) {
            oacc[nj][0] *= corr_a; oacc[nj][1] *= corr_a;
            oacc[nj][2] *= corr_b; oacc[nj][3] *= corr_b;
        }

        // ---- O += (Ph+Pl) * (Vh+Vl) : PhVh + PlVh + PhVl ----
        #pragma unroll
        for (int kb = 0; kb < 4; kb++) {
            uint32_t pa_h[4], pa_l[4];
            pack_hl(sacc[2 * kb][0], sacc[2 * kb][1], pa_h[0], pa_l[0]);
            pack_hl(sacc[2 * kb][2], sacc[2 * kb][3], pa_h[1], pa_l[1]);
            pack_hl(sacc[2 * kb + 1][0], sacc[2 * kb + 1][1], pa_h[2], pa_l[2]);
            pack_hl(sacc[2 * kb + 1][2], sacc[2 * kb + 1][3], pa_h[3], pa_l[3]);
            #pragma unroll
            for (int nout = 0; nout < 4; nout++) {
                uint32_t vr = kvb + 2 * AKV_T + (kb * 16 + v_krow) * APAD + nout * 16 + v_ncol;
                uint32_t rv[4];
                ldsm_x4_t(rv[0], rv[1], rv[2], rv[3], sbase + vr * 2);
                mma_bf16(oacc[2 * nout], pa_h, rv[0], rv[1]);
                mma_bf16(oacc[2 * nout], pa_l, rv[0], rv[1]);
                mma_bf16(oacc[2 * nout + 1], pa_h, rv[2], rv[3]);
                mma_bf16(oacc[2 * nout + 1], pa_l, rv[2], rv[3]);
                ldsm_x4_t(rv[0], rv[1], rv[2], rv[3], sbase + (vr + AKV_T) * 2);
                mma_bf16(oacc[2 * nout], pa_h, rv[0], rv[1]);
                mma_bf16(oacc[2 * nout + 1], pa_h, rv[2], rv[3]);
            }
        }
        __syncthreads();
    }

    // ---- epilogue: y = O / l, split hi/lo ----
    const float inv_a = 1.0f / l_a;
    const float inv_b = 1.0f / l_b;
    #pragma unroll
    for (int nj = 0; nj < 8; nj++) {
        int col = h * DH + nj * 8 + (lane & 3) * 2;
        size_t ra = (size_t)(b * T_SEQ + gr_a) * DMODEL + col;
        size_t rb2 = (size_t)(b * T_SEQ + gr_b) * DMODEL + col;
        uint32_t h0, l0, h1, l1;
        pack_hl(oacc[nj][0] * inv_a, oacc[nj][1] * inv_a, h0, l0);
        pack_hl(oacc[nj][2] * inv_b, oacc[nj][3] * inv_b, h1, l1);
        *(uint32_t*)(yh + ra) = h0;
        *(uint32_t*)(yl + ra) = l0;
        *(uint32_t*)(yh + rb2) = h1;
        *(uint32_t*)(yl + rb2) = l1;
    }
}

// ---------------------------------------------------------------------------
// fp32 -> (hi, lo) bf16 split
// ---------------------------------------------------------------------------
__global__ __launch_bounds__(256) void split_kernel(
    const float* __restrict__ in, __nv_bfloat16* __restrict__ hi,
    __nv_bfloat16* __restrict__ lo, int n4)
{
    int i = blockIdx.x * blockDim.x + threadIdx.x;
    if (i >= n4) return;
    float4 v = *(const float4*)(in + (size_t)i * 4);
    __nv_bfloat16 h[4], l[4];
    float f[4] = {v.x, v.y, v.z, v.w};
    #pragma unroll
    for (int k = 0; k < 4; ++k) {
        h[k] = __float2bfloat16(f[k]);
        l[k] = __float2bfloat16(f[k] - __bfloat162float(h[k]));
    }
    *(uint2*)(hi + (size_t)i * 4) = *(uint2*)h;
    *(uint2*)(lo + (size_t)i * 4) = *(uint2*)l;
}

// ---------------------------------------------------------------------------
// W [K,N] fp32 -> W^T (hi, lo) bf16 [N,K]
// ---------------------------------------------------------------------------
__global__ __launch_bounds__(256) void split_transpose_kernel(
    const float* __restrict__ W, __nv_bfloat16* __restrict__ hiT,
    __nv_bfloat16* __restrict__ loT, int K, int N)
{
    __shared__ float tile[32][33];
    const int tx = threadIdx.x;
    const int ty = threadIdx.y;
    const int k0 = blockIdx.y * 32;
    const int n0 = blockIdx.x * 32;
    #pragma unroll
    for (int r = 0; r < 32; r += 8)
        tile[ty + r][tx] = W[(size_t)(k0 + ty + r) * N + n0 + tx];
    __syncthreads();
    #pragma unroll
    for (int r = 0; r < 32; r += 8) {
        float v = tile[tx][ty + r];
        __nv_bfloat16 h = __float2bfloat16(v);
        __nv_bfloat16 l = __float2bfloat16(v - __bfloat162float(h));
        size_t o = (size_t)(n0 + ty + r) * K + k0 + tx;
        hiT[o] = h;
        loT[o] = l;
    }
}

// ---------------------------------------------------------------------------
extern "C" void kernel_launch(void* const* d_in, const int* in_sizes, int n_in,
                              void* d_out, int out_size)
{
    const float* x      = (const float*)d_in[0];
    const float* w_attn = (const float*)d_in[1];
    const float* b_attn = (const float*)d_in[2];
    const float* w_proj = (const float*)d_in[3];
    const float* b_proj = (const float*)d_in[4];
    float* out = (float*)d_out;

    __nv_bfloat16 *qkvh, *qkvl, *xh, *xl, *yh, *yl, *wah, *wal, *wph, *wpl;
    cudaGetSymbolAddress((void**)&qkvh, g_qkvh);
    cudaGetSymbolAddress((void**)&qkvl, g_qkvl);
    cudaGetSymbolAddress((void**)&xh, g_xh);
    cudaGetSymbolAddress((void**)&xl, g_xl);
    cudaGetSymbolAddress((void**)&yh, g_yh);
    cudaGetSymbolAddress((void**)&yl, g_yl);
    cudaGetSymbolAddress((void**)&wah, g_wah);
    cudaGetSymbolAddress((void**)&wal, g_wal);
    cudaGetSymbolAddress((void**)&wph, g_wph);
    cudaGetSymbolAddress((void**)&wpl, g_wpl);

    static bool attr_set = false;
    if (!attr_set) {
        cudaFuncSetAttribute(mma_attn_kernel,
                             cudaFuncAttributeMaxDynamicSharedMemorySize, ATTN_SMEM);
        cudaFuncSetAttribute(mma_gemm_kernel,
                             cudaFuncAttributeMaxDynamicSharedMemorySize, GEMM_SMEM);
        attr_set = true;
    }

    // 0) conversions
    {
        int n4 = (M_ROWS * DMODEL) / 4;
        split_kernel<<<(n4 + 255) / 256, 256>>>(x, xh, xl, n4);
        dim3 blk(32, 8);
        split_transpose_kernel<<<dim3(QKV_N / 32, DMODEL / 32), blk>>>(w_attn, wah, wal, DMODEL, QKV_N);
        split_transpose_kernel<<<dim3(DMODEL / 32, DMODEL / 32), blk>>>(w_proj, wph, wpl, DMODEL, DMODEL);
    }
    // 1) QKV GEMM -> bf16 hi/lo qkv
    {
        dim3 grid(QKV_N / 128, M_ROWS / 128);
        mma_gemm_kernel<<<grid, 256, GEMM_SMEM>>>(xh, xl, wah, wal, b_attn,
                                                  nullptr, qkvh, qkvl, QKV_N);
    }
    // 2) causal flash attention on HMMA -> bf16 hi/lo y
    {
        dim3 grid(T_SEQ / 128, BATCH * NH);   // (16, 48)
        mma_attn_kernel<<<grid, 256, ATTN_SMEM>>>(qkvh, qkvl, yh, yl);
    }
    // 3) out projection -> fp32 out
    {
        dim3 grid(DMODEL / 128, M_ROWS / 128);
        mma_gemm_kernel<<<grid, 256, GEMM_SMEM>>>(yh, yl, wph, wpl, b_proj,
                                                  out, nullptr, nullptr, DMODEL);
    }
}

// round 11
// speedup vs baseline: 1.0330x; 1.0330x over previous
#include <cuda_runtime.h>
#include <cuda_bf16.h>
#include <cstdint>
#include <math.h>

#define BATCH 4
#define T_SEQ 2048
#define NH 12
#define DMODEL 768
#define DH 64
#define M_ROWS (BATCH * T_SEQ)          // 8192
#define QKV_N (3 * DMODEL)              // 2304
#define GK DMODEL                       // GEMM K = 768

// ------------------------- scratch (static, allocation-free) ---------------
__device__ __nv_bfloat16 g_qkvh[(size_t)M_ROWS * QKV_N];
__device__ __nv_bfloat16 g_qkvl[(size_t)M_ROWS * QKV_N];
__device__ __nv_bfloat16 g_xh[(size_t)M_ROWS * DMODEL];
__device__ __nv_bfloat16 g_xl[(size_t)M_ROWS * DMODEL];
__device__ __nv_bfloat16 g_yh[(size_t)M_ROWS * DMODEL];
__device__ __nv_bfloat16 g_yl[(size_t)M_ROWS * DMODEL];
__device__ __nv_bfloat16 g_wah[(size_t)QKV_N * DMODEL];  // w_attn^T [2304,768]
__device__ __nv_bfloat16 g_wal[(size_t)QKV_N * DMODEL];
__device__ __nv_bfloat16 g_wph[(size_t)DMODEL * DMODEL]; // w_proj^T [768,768]
__device__ __nv_bfloat16 g_wpl[(size_t)DMODEL * DMODEL];

// ------------------------- helpers -----------------------------------------
__device__ __forceinline__ uint32_t smem_u32(const void* p) {
    uint32_t a;
    asm("{ .reg .u64 t; cvta.to.shared.u64 t, %1; cvt.u32.u64 %0, t; }" : "=r"(a) : "l"(p));
    return a;
}
__device__ __forceinline__ void cp16(uint32_t dst, const void* src) {
    asm volatile("cp.async.cg.shared.global [%0], [%1], 16;" :: "r"(dst), "l"(src));
}
#define CP_COMMIT() asm volatile("cp.async.commit_group;" ::: "memory")
#define CP_WAIT0()  asm volatile("cp.async.wait_group 0;" ::: "memory")

__device__ __forceinline__ void ldsm_x4(uint32_t& r0, uint32_t& r1,
                                        uint32_t& r2, uint32_t& r3, uint32_t addr) {
    asm volatile("ldmatrix.sync.aligned.m8n8.x4.shared.b16 {%0,%1,%2,%3}, [%4];"
                 : "=r"(r0), "=r"(r1), "=r"(r2), "=r"(r3) : "r"(addr));
}
__device__ __forceinline__ void ldsm_x4_t(uint32_t& r0, uint32_t& r1,
                                          uint32_t& r2, uint32_t& r3, uint32_t addr) {
    asm volatile("ldmatrix.sync.aligned.m8n8.x4.trans.shared.b16 {%0,%1,%2,%3}, [%4];"
                 : "=r"(r0), "=r"(r1), "=r"(r2), "=r"(r3) : "r"(addr));
}
__device__ __forceinline__ void mma_bf16(float* c, const uint32_t* a,
                                         uint32_t b0, uint32_t b1) {
    asm volatile(
        "mma.sync.aligned.m16n8k16.row.col.f32.bf16.bf16.f32 "
        "{%0,%1,%2,%3}, {%4,%5,%6,%7}, {%8,%9}, {%0,%1,%2,%3};"
        : "+f"(c[0]), "+f"(c[1]), "+f"(c[2]), "+f"(c[3])
        : "r"(a[0]), "r"(a[1]), "r"(a[2]), "r"(a[3]), "r"(b0), "r"(b1));
}
__device__ __forceinline__ void pack_hl(float f0, float f1, uint32_t& h, uint32_t& l) {
    __nv_bfloat16 h0 = __float2bfloat16(f0), h1 = __float2bfloat16(f1);
    __nv_bfloat162 hh; hh.x = h0; hh.y = h1;
    h = *(uint32_t*)&hh;
    __nv_bfloat162 ll;
    ll.x = __float2bfloat16(f0 - __bfloat162float(h0));
    ll.y = __float2bfloat16(f1 - __bfloat162float(h1));
    l = *(uint32_t*)&ll;
}

// ---------------------------------------------------------------------------
// HMMA GEMM, bf16x3 (fused single-load): C = Ah*Bh + Al*Bh + Ah*Bl + bias
// K-chunk 96 (8 chunks), single-buffered cp.async, 2 CTAs/SM.
// 256 threads = 8 warps (4M x 2N), warp tile 32x64.
// ---------------------------------------------------------------------------
#define GPAD 104                          // bf16 row stride (208 B); 13 granules (odd)
#define GTILE_E (128 * GPAD)
#define GOAH 0
#define GOAL GTILE_E
#define GOBH (2 * GTILE_E)
#define GOBL (3 * GTILE_E)
#define GEMM_SMEM (4 * GTILE_E * 2)       // 106496 bytes

__global__ __launch_bounds__(256, 2) void mma_gemm_kernel(
    const __nv_bfloat16* __restrict__ Ah, const __nv_bfloat16* __restrict__ Al,
    const __nv_bfloat16* __restrict__ Bh, const __nv_bfloat16* __restrict__ Bl,
    const float* __restrict__ bias, float* __restrict__ C,
    __nv_bfloat16* __restrict__ Ch, __nv_bfloat16* __restrict__ Cl, int N)
{
    extern __shared__ __nv_bfloat16 gsm[];
    const int tid  = threadIdx.x;
    const int wid  = tid >> 5;
    const int lane = tid & 31;
    const int m0 = blockIdx.y * 128;
    const int n0 = blockIdx.x * 128;
    const int warp_m = (wid >> 1) * 32;
    const int warp_n = (wid & 1) * 64;
    const uint32_t sbase = smem_u32(gsm);

    const int a_row = (lane & 15);
    const int a_coff = (lane >> 4) * 8;
    const int b_row = (lane & 7) + ((lane >> 3) & 1) * 8;
    const int b_coff = ((lane >> 4) & 1) * 8;

    float acc[2][8][4];
    #pragma unroll
    for (int mi = 0; mi < 2; mi++)
        #pragma unroll
        for (int nj = 0; nj < 8; nj++)
            #pragma unroll
            for (int q = 0; q < 4; q++) acc[mi][nj][q] = 0.0f;

    #pragma unroll 1
    for (int kc = 0; kc < GK; kc += 96) {
        __syncthreads();
        // 4 tiles x 128 rows x 96 cols = 6144 16B granules; 24 per thread
        #pragma unroll
        for (int it = 0; it < 24; it++) {
            int idx = tid + it * 256;          // 0..6143
            int tile = idx / 1536;             // 0:Ah 1:Al 2:Bh 3:Bl
            int rem = idx - tile * 1536;
            int row = rem / 12;                // 0..127
            int g   = rem - row * 12;          // 0..11
            const __nv_bfloat16* sp =
                (tile == 0) ? Ah : (tile == 1) ? Al : (tile == 2) ? Bh : Bl;
            int rbase = (tile < 2) ? m0 : n0;
            cp16(sbase + (uint32_t)(tile * GTILE_E + row * GPAD + g * 8) * 2,
                 sp + (size_t)(rbase + row) * GK + kc + g * 8);
        }
        CP_COMMIT();
        CP_WAIT0();
        __syncthreads();

        #pragma unroll
        for (int ks = 0; ks < 6; ks++) {
            const int k0 = ks * 16;
            uint32_t rah[2][4], ral[2][4];
            #pragma unroll
            for (int mi = 0; mi < 2; mi++) {
                uint32_t ar = (warp_m + mi * 16 + a_row) * GPAD + k0 + a_coff;
                ldsm_x4(rah[mi][0], rah[mi][1], rah[mi][2], rah[mi][3],
                        sbase + (GOAH + ar) * 2);
                ldsm_x4(ral[mi][0], ral[mi][1], ral[mi][2], ral[mi][3],
                        sbase + (GOAL + ar) * 2);
            }
            #pragma unroll
            for (int nb = 0; nb < 4; nb++) {
                uint32_t br = (warp_n + nb * 16 + b_row) * GPAD + k0 + b_coff;
                uint32_t rb[4];
                ldsm_x4(rb[0], rb[1], rb[2], rb[3], sbase + (GOBH + br) * 2);
                #pragma unroll
                for (int mi = 0; mi < 2; mi++)
                    #pragma unroll
                    for (int lo = 0; lo < 2; lo++) {
                        mma_bf16(acc[mi][2 * nb + lo], rah[mi], rb[lo], rb[lo + 2]);
                        mma_bf16(acc[mi][2 * nb + lo], ral[mi], rb[lo], rb[lo + 2]);
                    }
                ldsm_x4(rb[0], rb[1], rb[2], rb[3], sbase + (GOBL + br) * 2);
                #pragma unroll
                for (int mi = 0; mi < 2; mi++)
                    #pragma unroll
                    for (int lo = 0; lo < 2; lo++)
                        mma_bf16(acc[mi][2 * nb + lo], rah[mi], rb[lo], rb[lo + 2]);
            }
        }
    }

    const int mrow = m0 + warp_m + (lane >> 2);
    const int ncol = n0 + warp_n + (lane & 3) * 2;
    #pragma unroll
    for (int mi = 0; mi < 2; mi++) {
        #pragma unroll
        for (int nj = 0; nj < 8; nj++) {
            int r = mrow + mi * 16;
            int c = ncol + nj * 8;
            float bv0 = bias[c], bv1 = bias[c + 1];
            float v00 = acc[mi][nj][0] + bv0, v01 = acc[mi][nj][1] + bv1;
            float v10 = acc[mi][nj][2] + bv0, v11 = acc[mi][nj][3] + bv1;
            if (Cl) {
                uint32_t h0, l0, h1, l1;
                pack_hl(v00, v01, h0, l0);
                pack_hl(v10, v11, h1, l1);
                *(uint32_t*)(Ch + (size_t)r * N + c) = h0;
                *(uint32_t*)(Cl + (size_t)r * N + c) = l0;
                *(uint32_t*)(Ch + (size_t)(r + 8) * N + c) = h1;
                *(uint32_t*)(Cl + (size_t)(r + 8) * N + c) = l1;
            } else {
                *(float2*)(C + (size_t)r * N + c) = make_float2(v00, v01);
                *(float2*)(C + (size_t)(r + 8) * N + c) = make_float2(v10, v11);
            }
        }
    }
}

// ---------------------------------------------------------------------------
// HMMA flash attention (causal), bf16x3, 128-row K/V super-tiles with two
// 64-row compute sub-tiles per load phase. Single-buffered, 2 CTAs/SM.
// Grid (T/128, B*NH), 256 threads = 8 warps x 16 Q-rows.
// ---------------------------------------------------------------------------
#define APAD 72
#define AT128 (128 * APAD)               // one 128-row tile
#define AQH 0
#define AQL AT128
#define AKH (2 * AT128)
#define AKL (3 * AT128)
#define AVH (4 * AT128)
#define AVL (5 * AT128)
#define ATTN_SMEM (6 * AT128 * 2)        // 110592 bytes

__global__ __launch_bounds__(256, 2) void mma_attn_kernel(
    const __nv_bfloat16* __restrict__ qkvh, const __nv_bfloat16* __restrict__ qkvl,
    __nv_bfloat16* __restrict__ yh, __nv_bfloat16* __restrict__ yl)
{
    extern __shared__ __nv_bfloat16 sm[];
    const int tid = threadIdx.x;
    const int wid = tid >> 5;
    const int lane = tid & 31;
    const int qt = gridDim.x - 1 - blockIdx.x;     // heavy tiles first
    const int bh = blockIdx.y;
    const int b = bh / NH;
    const int h = bh % NH;
    const size_t base = (size_t)b * T_SEQ * QKV_N;
    const int qoff = h * DH;
    const int koff = DMODEL + h * DH;
    const int voff = 2 * DMODEL + h * DH;
    const uint32_t sbase = smem_u32(sm);

    const int a_row = (lane & 15);
    const int a_coff = (lane >> 4) * 8;
    const int b_row = (lane & 7) + ((lane >> 3) & 1) * 8;
    const int b_coff = ((lane >> 4) & 1) * 8;
    const int v_krow = ((lane >> 3) & 1) * 8 + (lane & 7);
    const int v_ncol = ((lane >> 4) & 1) * 8;

    // ---- load Q tile (hi/lo) via cp.async ----
    #pragma unroll
    for (int it = 0; it < 4; it++) {
        int idx = tid + it * 256;        // 0..1023
        int row = idx >> 3, g = idx & 7;
        size_t goff = base + (size_t)(qt * 128 + row) * QKV_N + qoff + g * 8;
        uint32_t so = (uint32_t)(row * APAD + g * 8) * 2;
        cp16(sbase + so, qkvh + goff);
        cp16(sbase + AQL * 2 + so, qkvl + goff);
    }
    CP_COMMIT();

    float oacc[8][4];
    #pragma unroll
    for (int nj = 0; nj < 8; nj++)
        #pragma unroll
        for (int q = 0; q < 4; q++) oacc[nj][q] = 0.0f;
    float m_a = -1e30f, m_b = -1e30f, l_a = 0.0f, l_b = 0.0f;

    const int gr_a = qt * 128 + wid * 16 + (lane >> 2);
    const int gr_b = gr_a + 8;
    const int nkt2 = qt + 1;             // 128-row super-tiles

    #pragma unroll 1
    for (int ktL = 0; ktL < nkt2; ktL++) {
        __syncthreads();
        // ---- load 128-row K/V (hi/lo): 4 tiles x 128 rows x 8 granules ----
        #pragma unroll
        for (int it = 0; it < 16; it++) {
            int idx = tid + it * 256;     // 0..4095
            int tile = idx >> 10;         // 0:Kh 1:Kl 2:Vh 3:Vl
            int r = (idx >> 3) & 127;
            int g = idx & 7;
            const __nv_bfloat16* src = (tile & 1) ? qkvl : qkvh;
            int off = (tile < 2) ? koff : voff;
            int dsto = AKH + tile * AT128;
            cp16(sbase + (uint32_t)(dsto + r * APAD + g * 8) * 2,
                 src + base + (size_t)(ktL * 128 + r) * QKV_N + off + g * 8);
        }
        CP_COMMIT();
        CP_WAIT0();
        __syncthreads();

        const bool diag_super = (ktL == qt);
        #pragma unroll 1
        for (int sub = 0; sub < 2; sub++) {
            const int rowoff = sub * 64;

            // ---- S = Qh*Kh + Ql*Kh + Qh*Kl ----
            float sacc[8][4];
            #pragma unroll
            for (int nj = 0; nj < 8; nj++)
                #pragma unroll
                for (int q = 0; q < 4; q++) sacc[nj][q] = 0.0f;

            #pragma unroll
            for (int ks = 0; ks < 4; ks++) {
                const int k0 = ks * 16;
                uint32_t qh[4], ql[4];
                uint32_t qr = (wid * 16 + a_row) * APAD + k0 + a_coff;
                ldsm_x4(qh[0], qh[1], qh[2], qh[3], sbase + qr * 2);
                ldsm_x4(ql[0], ql[1], ql[2], ql[3], sbase + (AQL + qr) * 2);
                #pragma unroll
                for (int nb = 0; nb < 4; nb++) {
                    uint32_t br = AKH + (rowoff + nb * 16 + b_row) * APAD + k0 + b_coff;
                    uint32_t rb[4];
                    ldsm_x4(rb[0], rb[1], rb[2], rb[3], sbase + br * 2);
                    #pragma unroll
                    for (int lo = 0; lo < 2; lo++) {
                        mma_bf16(sacc[2 * nb + lo], qh, rb[lo], rb[lo + 2]);
                        mma_bf16(sacc[2 * nb + lo], ql, rb[lo], rb[lo + 2]);
                    }
                    ldsm_x4(rb[0], rb[1], rb[2], rb[3], sbase + (br + AT128) * 2);
                    #pragma unroll
                    for (int lo = 0; lo < 2; lo++)
                        mma_bf16(sacc[2 * nb + lo], qh, rb[lo], rb[lo + 2]);
                }
            }

            // ---- scale + causal mask ----
            #pragma unroll
            for (int nj = 0; nj < 8; nj++) {
                #pragma unroll
                for (int q = 0; q < 4; q++) sacc[nj][q] *= 0.125f;
                if (diag_super) {
                    int gc = ktL * 128 + rowoff + nj * 8 + (lane & 3) * 2;
                    if (gc > gr_a)     sacc[nj][0] = -1e30f;
                    if (gc + 1 > gr_a) sacc[nj][1] = -1e30f;
                    if (gc > gr_b)     sacc[nj][2] = -1e30f;
                    if (gc + 1 > gr_b) sacc[nj][3] = -1e30f;
                }
            }

            // ---- online softmax ----
            float mx_a = -1e30f, mx_b = -1e30f;
            #pragma unroll
            for (int nj = 0; nj < 8; nj++) {
                mx_a = fmaxf(mx_a, fmaxf(sacc[nj][0], sacc[nj][1]));
                mx_b = fmaxf(mx_b, fmaxf(sacc[nj][2], sacc[nj][3]));
            }
            mx_a = fmaxf(mx_a, __shfl_xor_sync(0xffffffffu, mx_a, 1));
            mx_a = fmaxf(mx_a, __shfl_xor_sync(0xffffffffu, mx_a, 2));
            mx_b = fmaxf(mx_b, __shfl_xor_sync(0xffffffffu, mx_b, 1));
            mx_b = fmaxf(mx_b, __shfl_xor_sync(0xffffffffu, mx_b, 2));
            float mn_a = fmaxf(m_a, mx_a), mn_b = fmaxf(m_b, mx_b);
            float corr_a = __expf(m_a - mn_a), corr_b = __expf(m_b - mn_b);
            float sum_a = 0.0f, sum_b = 0.0f;
            #pragma unroll
            for (int nj = 0; nj < 8; nj++) {
                sacc[nj][0] = __expf(sacc[nj][0] - mn_a);
                sacc[nj][1] = __expf(sacc[nj][1] - mn_a);
                sacc[nj][2] = __expf(sacc[nj][2] - mn_b);
                sacc[nj][3] = __expf(sacc[nj][3] - mn_b);
                sum_a += sacc[nj][0] + sacc[nj][1];
                sum_b += sacc[nj][2] + sacc[nj][3];
            }
            sum_a += __shfl_xor_sync(0xffffffffu, sum_a, 1);
            sum_a += __shfl_xor_sync(0xffffffffu, sum_a, 2);
            sum_b += __shfl_xor_sync(0xffffffffu, sum_b, 1);
            sum_b += __shfl_xor_sync(0xffffffffu, sum_b, 2);
            l_a = l_a * corr_a + sum_a;
            l_b = l_b * corr_b + sum_b;
            m_a = mn_a; m_b = mn_b;
            #pragma unroll
            for (int nj = 0; nj < 8; nj++) {
                oacc[nj][0] *= corr_a; oacc[nj][1] *= corr_a;
                oacc[nj][2] *= corr_b; oacc[nj][3] *= corr_b;
            }

            // ---- O += (Ph+Pl) * (Vh+Vl) : PhVh + PlVh + PhVl ----
            #pragma unroll
            for (int kb = 0; kb < 4; kb++) {
                uint32_t pa_h[4], pa_l[4];
                pack_hl(sacc[2 * kb][0], sacc[2 * kb][1], pa_h[0], pa_l[0]);
                pack_hl(sacc[2 * kb][2], sacc[2 * kb][3], pa_h[1], pa_l[1]);
                pack_hl(sacc[2 * kb + 1][0], sacc[2 * kb + 1][1], pa_h[2], pa_l[2]);
                pack_hl(sacc[2 * kb + 1][2], sacc[2 * kb + 1][3], pa_h[3], pa_l[3]);
                #pragma unroll
                for (int nout = 0; nout < 4; nout++) {
                    uint32_t vr = AVH + (rowoff + kb * 16 + v_krow) * APAD + nout * 16 + v_ncol;
                    uint32_t rv[4];
                    ldsm_x4_t(rv[0], rv[1], rv[2], rv[3], sbase + vr * 2);
                    mma_bf16(oacc[2 * nout], pa_h, rv[0], rv[1]);
                    mma_bf16(oacc[2 * nout], pa_l, rv[0], rv[1]);
                    mma_bf16(oacc[2 * nout + 1], pa_h, rv[2], rv[3]);
                    mma_bf16(oacc[2 * nout + 1], pa_l, rv[2], rv[3]);
                    ldsm_x4_t(rv[0], rv[1], rv[2], rv[3], sbase + (vr + AT128) * 2);
                    mma_bf16(oacc[2 * nout], pa_h, rv[0], rv[1]);
                    mma_bf16(oacc[2 * nout + 1], pa_h, rv[2], rv[3]);
                }
            }
        }
    }

    // ---- epilogue: y = O / l, split hi/lo ----
    const float inv_a = 1.0f / l_a;
    const float inv_b = 1.0f / l_b;
    #pragma unroll
    for (int nj = 0; nj < 8; nj++) {
        int col = h * DH + nj * 8 + (lane & 3) * 2;
        size_t ra = (size_t)(b * T_SEQ + gr_a) * DMODEL + col;
        size_t rb2 = (size_t)(b * T_SEQ + gr_b) * DMODEL + col;
        uint32_t h0, l0, h1, l1;
        pack_hl(oacc[nj][0] * inv_a, oacc[nj][1] * inv_a, h0, l0);
        pack_hl(oacc[nj][2] * inv_b, oacc[nj][3] * inv_b, h1, l1);
        *(uint32_t*)(yh + ra) = h0;
        *(uint32_t*)(yl + ra) = l0;
        *(uint32_t*)(yh + rb2) = h1;
        *(uint32_t*)(yl + rb2) = l1;
    }
}

// ---------------------------------------------------------------------------
// fp32 -> (hi, lo) bf16 split
// ---------------------------------------------------------------------------
__global__ __launch_bounds__(256) void split_kernel(
    const float* __restrict__ in, __nv_bfloat16* __restrict__ hi,
    __nv_bfloat16* __restrict__ lo, int n4)
{
    int i = blockIdx.x * blockDim.x + threadIdx.x;
    if (i >= n4) return;
    float4 v = *(const float4*)(in + (size_t)i * 4);
    __nv_bfloat16 h[4], l[4];
    float f[4] = {v.x, v.y, v.z, v.w};
    #pragma unroll
    for (int k = 0; k < 4; ++k) {
        h[k] = __float2bfloat16(f[k]);
        l[k] = __float2bfloat16(f[k] - __bfloat162float(h[k]));
    }
    *(uint2*)(hi + (size_t)i * 4) = *(uint2*)h;
    *(uint2*)(lo + (size_t)i * 4) = *(uint2*)l;
}

// ---------------------------------------------------------------------------
// W [K,N] fp32 -> W^T (hi, lo) bf16 [N,K]
// ---------------------------------------------------------------------------
__global__ __launch_bounds__(256) void split_transpose_kernel(
    const float* __restrict__ W, __nv_bfloat16* __restrict__ hiT,
    __nv_bfloat16* __restrict__ loT, int K, int N)
{
    __shared__ float tile[32][33];
    const int tx = threadIdx.x;
    const int ty = threadIdx.y;
    const int k0 = blockIdx.y * 32;
    const int n0 = blockIdx.x * 32;
    #pragma unroll
    for (int r = 0; r < 32; r += 8)
        tile[ty + r][tx] = W[(size_t)(k0 + ty + r) * N + n0 + tx];
    __syncthreads();
    #pragma unroll
    for (int r = 0; r < 32; r += 8) {
        float v = tile[tx][ty + r];
        __nv_bfloat16 h = __float2bfloat16(v);
        __nv_bfloat16 l = __float2bfloat16(v - __bfloat162float(h));
        size_t o = (size_t)(n0 + ty + r) * K + k0 + tx;
        hiT[o] = h;
        loT[o] = l;
    }
}

// ---------------------------------------------------------------------------
extern "C" void kernel_launch(void* const* d_in, const int* in_sizes, int n_in,
                              void* d_out, int out_size)
{
    const float* x      = (const float*)d_in[0];
    const float* w_attn = (const float*)d_in[1];
    const float* b_attn = (const float*)d_in[2];
    const float* w_proj = (const float*)d_in[3];
    const float* b_proj = (const float*)d_in[4];
    float* out = (float*)d_out;

    __nv_bfloat16 *qkvh, *qkvl, *xh, *xl, *yh, *yl, *wah, *wal, *wph, *wpl;
    cudaGetSymbolAddress((void**)&qkvh, g_qkvh);
    cudaGetSymbolAddress((void**)&qkvl, g_qkvl);
    cudaGetSymbolAddress((void**)&xh, g_xh);
    cudaGetSymbolAddress((void**)&xl, g_xl);
    cudaGetSymbolAddress((void**)&yh, g_yh);
    cudaGetSymbolAddress((void**)&yl, g_yl);
    cudaGetSymbolAddress((void**)&wah, g_wah);
    cudaGetSymbolAddress((void**)&wal, g_wal);
    cudaGetSymbolAddress((void**)&wph, g_wph);
    cudaGetSymbolAddress((void**)&wpl, g_wpl);

    static bool attr_set = false;
    if (!attr_set) {
        cudaFuncSetAttribute(mma_attn_kernel,
                             cudaFuncAttributeMaxDynamicSharedMemorySize, ATTN_SMEM);
        cudaFuncSetAttribute(mma_gemm_kernel,
                             cudaFuncAttributeMaxDynamicSharedMemorySize, GEMM_SMEM);
        attr_set = true;
    }

    // 0) conversions
    {
        int n4 = (M_ROWS * DMODEL) / 4;
        split_kernel<<<(n4 + 255) / 256, 256>>>(x, xh, xl, n4);
        dim3 blk(32, 8);
        split_transpose_kernel<<<dim3(QKV_N / 32, DMODEL / 32), blk>>>(w_attn, wah, wal, DMODEL, QKV_N);
        split_transpose_kernel<<<dim3(DMODEL / 32, DMODEL / 32), blk>>>(w_proj, wph, wpl, DMODEL, DMODEL);
    }
    // 1) QKV GEMM -> bf16 hi/lo qkv
    {
        dim3 grid(QKV_N / 128, M_ROWS / 128);
        mma_gemm_kernel<<<grid, 256, GEMM_SMEM>>>(xh, xl, wah, wal, b_attn,
                                                  nullptr, qkvh, qkvl, QKV_N);
    }
    // 2) causal flash attention on HMMA -> bf16 hi/lo y
    {
        dim3 grid(T_SEQ / 128, BATCH * NH);   // (16, 48)
        mma_attn_kernel<<<grid, 256, ATTN_SMEM>>>(qkvh, qkvl, yh, yl);
    }
    // 3) out projection -> fp32 out
    {
        dim3 grid(DMODEL / 128, M_ROWS / 128);
        mma_gemm_kernel<<<grid, 256, GEMM_SMEM>>>(yh, yl, wph, wpl, b_proj,
                                                  out, nullptr, nullptr, DMODEL);
    }
}